// round 10
// baseline (speedup 1.0000x reference)
#include <cuda_runtime.h>
#include <cstdint>

// FirstFFTLinearLayer: 64-point forward complex DFT along dim 1 of
// [B=16, N=64, H=256, W=256] f32 (separate real/imag inputs).
// Output: REAL PART only, f32, layout [B, N, H, W] (established R1-R9;
// R9 passed at rel_err 2.1e-7).
//
// R9 profile: DRAM=81.7%, 6.47 TB/s, traffic already minimal (768 MB).
// This revision targets bandwidth efficiency only:
//  - __ldcs/__stcs streaming hints (zero reuse -> evict-first, no L2
//    write-allocate pollution)
//  - stage-1 butterflies interleaved with the load pairs so compute
//    overlaps in-flight loads and the DRAM stream stays dense.

#define HW 65536          // H*W
#define NFFT 64
#define BATCH 16
#define NPIX (BATCH * HW) // 1,048,576

__global__ __launch_bounds__(128)
void fft64_kernel(const float* __restrict__ re,
                  const float* __restrict__ im,
                  float* __restrict__ out) {
    __shared__ float2 tw[NFFT];
    {
        int t = threadIdx.x;
        if (t < NFFT) {
            float s, c;
            // exp(-2*pi*i*t/64) = cos(pi t/32) - i sin(pi t/32)
            sincospif(-(float)t * (1.0f / 32.0f), &s, &c);
            tw[t] = make_float2(c, s);
        }
    }
    __syncthreads();

    int idx = blockIdx.x * blockDim.x + threadIdx.x;
    int s_  = idx & (HW - 1);
    int b   = idx >> 16;
    const size_t base = (size_t)b * (NFFT * (size_t)HW) + (size_t)s_;

    const float* pr = re + base;
    const float* pi_ = im + base;

    float xr[NFFT], xi[NFFT];

    // Load pairs (j, j+32) and do the stage-64 butterfly immediately:
    // each butterfly depends on only its own 4 loads, so compute overlaps
    // the remaining in-flight loads instead of waiting for all 128.
#pragma unroll
    for (int j = 0; j < 32; j++) {
        float ur = __ldcs(pr  + (size_t)j * HW);
        float vr = __ldcs(pr  + (size_t)(j + 32) * HW);
        float ui = __ldcs(pi_ + (size_t)j * HW);
        float vi = __ldcs(pi_ + (size_t)(j + 32) * HW);
        xr[j] = ur + vr;
        xi[j] = ui + vi;
        float dr = ur - vr, di = ui - vi;
        float2 w = tw[j];  // step = 1 for the m=64 stage
        xr[j + 32] = dr * w.x - di * w.y;
        xi[j + 32] = dr * w.y + di * w.x;
    }

    // Remaining radix-2 DIF stages (m = 32 .. 2), fully unrolled.
#define FFT_STAGE(M)                                                      \
    {                                                                     \
        constexpr int m_    = (M);                                        \
        constexpr int half_ = m_ / 2;                                     \
        constexpr int step_ = NFFT / m_;                                  \
        _Pragma("unroll")                                                 \
        for (int k = 0; k < NFFT; k += m_) {                              \
            _Pragma("unroll")                                             \
            for (int j = 0; j < half_; j++) {                             \
                float ur = xr[k + j],         ui = xi[k + j];             \
                float vr = xr[k + j + half_], vi = xi[k + j + half_];     \
                xr[k + j] = ur + vr;                                      \
                xi[k + j] = ui + vi;                                      \
                float dr = ur - vr, di = ui - vi;                         \
                float2 w = tw[(j * step_) & (NFFT - 1)];                  \
                xr[k + j + half_] = dr * w.x - di * w.y;                  \
                xi[k + j + half_] = dr * w.y + di * w.x;                  \
            }                                                             \
        }                                                                 \
    }

    FFT_STAGE(32)
    FFT_STAGE(16)
    FFT_STAGE(8)
    FFT_STAGE(4)
    FFT_STAGE(2)
#undef FFT_STAGE

    // X[k] sits at register slot brev6(k); store REAL PART only, streaming.
    float* o = out + base;
#pragma unroll
    for (int k = 0; k < NFFT; k++) {
        int p = (int)(__brev((unsigned)k) >> 26);  // 6-bit bit-reverse
        __stcs(o + (size_t)k * HW, xr[p]);
    }
}

extern "C" void kernel_launch(void* const* d_in, const int* in_sizes, int n_in,
                              void* d_out, int out_size) {
    // Weight = smallest input (unused); remaining two in d_in order = (re, im).
    int wmin = 0;
    for (int i = 1; i < n_in; i++)
        if (in_sizes[i] < in_sizes[wmin]) wmin = i;

    const float* adc_real = nullptr;
    const float* adc_imag = nullptr;
    for (int i = 0; i < n_in; i++) {
        if (i == wmin) continue;
        if (!adc_real)      adc_real = (const float*)d_in[i];
        else if (!adc_imag) adc_imag = (const float*)d_in[i];
    }
    if (!adc_real || !adc_imag) return;

    float* out = (float*)d_out;
    const int threads = 128;
    const int blocks  = NPIX / threads;  // 8192
    fft64_kernel<<<blocks, threads>>>(adc_real, adc_imag, out);
}